// round 11
// baseline (speedup 1.0000x reference)
#include <cuda_runtime.h>
#include <math.h>

#define BB 4
#define HH 544
#define WW 960
#define H2 272
#define W2 480
#define MD 24

#define NCC_BLOCKS 544          // BB * H2/2
#define TILEK_BLOCKS 4352       // 8 x 136 x 4  (120x4 tiles)
#define TOTAL_BLOCKS 4896       // NCC + TILE, ncc = every 9th block

// ---------------- scratch (no allocations allowed) ----------------
__device__ float g_lg[BB * H2 * W2];
__device__ float g_rg[BB * H2 * W2];
// accumulators padded to one 128B line each to avoid LTS atomic serialization
// idx: 0 gtNum 1 gtDen 2 photoNum 3 photoDen 4 signSum 5 magSum 6 activeSum 7 smx 8 smy
__device__ double g_acc[9 * 16];
__device__ int g_counter;   // zero-initialized; self-resetting

// ---------------- helpers ----------------
__device__ __forceinline__ float blockReduceSum(float v, float* sbuf) {
    int tid = threadIdx.x;
    int lane = tid & 31, wid = tid >> 5;
#pragma unroll
    for (int o = 16; o > 0; o >>= 1) v += __shfl_down_sync(0xffffffffu, v, o);
    if (lane == 0) sbuf[wid] = v;
    __syncthreads();
    int nw = (blockDim.x + 31) >> 5;
    v = (tid < nw) ? sbuf[tid] : 0.f;
    if (wid == 0) {
#pragma unroll
        for (int o = 16; o > 0; o >>= 1) v += __shfl_down_sync(0xffffffffu, v, o);
    }
    __syncthreads();
    return v;  // valid at tid 0
}

// ---------------- kernels ----------------
// half-res grayscale + accumulator/counter zeroing (block 0)
__global__ void downsample_kernel(const float* __restrict__ left,
                                  const float* __restrict__ right) {
    if (blockIdx.x == 0) {
        if (threadIdx.x < 9 * 16) g_acc[threadIdx.x] = 0.0;
        if (threadIdx.x == 0) g_counter = 0;
    }
    int i = blockIdx.x * blockDim.x + threadIdx.x;
    const int NPAIR = W2 / 2;  // 240
    if (i >= BB * H2 * NPAIR) return;
    int px = i % NPAIR;
    int y = (i / NPAIR) % H2;
    int b = i / (NPAIR * H2);
    float l0 = 0.f, l1 = 0.f, r0 = 0.f, r1 = 0.f;
#pragma unroll
    for (int c = 0; c < 3; c++) {
        int base = ((b * 3 + c) * HH + 2 * y) * WW + 4 * px;
        float4 a0 = *(const float4*)(left + base);
        float4 a1 = *(const float4*)(left + base + WW);
        l0 += (a0.x + a0.y + a1.x + a1.y);
        l1 += (a0.z + a0.w + a1.z + a1.w);
        float4 b0 = *(const float4*)(right + base);
        float4 b1 = *(const float4*)(right + base + WW);
        r0 += (b0.x + b0.y + b1.x + b1.y);
        r1 += (b0.z + b0.w + b1.z + b1.w);
    }
    const float S = 0.25f / 3.0f;
    int o = (b * H2 + y) * W2 + 2 * px;
    *(float2*)(g_lg + o) = make_float2(l0 * S, l1 * S);
    *(float2*)(g_rg + o) = make_float2(r0 * S, r1 * S);
}

// Heterogeneous mega-kernel: blockIdx.x % 9 == 0 -> NCC block (row-pair search
// + sign/mag, results never touch global); otherwise -> photometric/GT/smooth
// tile block (120x4, stride-1 smem). Crossbar-bound and DRAM-bound blocks
// co-reside per SM -> overlap without streams. Last block finalizes.
__global__ void __launch_bounds__(480, 2) mega_kernel(
        const float* __restrict__ pred,
        const float* __restrict__ gt,
        const float* __restrict__ conf,
        const float* __restrict__ occ,
        const float* __restrict__ left,
        const float* __restrict__ right,
        float* __restrict__ out) {
    __shared__ __align__(16) float sm[16656];
    __shared__ int lastFlag;
    float* sbuf = sm + 16640;   // 16 floats, disjoint from both layouts
    int bid = blockIdx.x;
    int tid = threadIdx.x;

    if (bid % 9 == 0) {
        // ================= NCC path =================
        float* rgS   = sm;             // [12][528], row r at rgS + r*528, idx col+24
        float* crp0  = sm + 6336;      // [560] idx col+40
        float* cr2p0 = sm + 6896;
        float* crp1  = sm + 7456;
        float* cr2p1 = sm + 8016;
        float* Hcr0  = sm + 8576;      // [528] at u = idx-24
        float* Hcr20 = sm + 9104;
        float* Hcr1  = sm + 9632;
        float* Hcr21 = sm + 10160;
        float* ccS   = sm + 10688;     // [2][6][496]: rr*2976 + j*496 + (col+8)
        float* clp0  = ccS;            // setup-only aliases (560 each)
        float* cl2p0 = ccS + 560;
        float* clp1  = ccS + 1120;
        float* cl2p1 = ccS + 1680;
        const float NORM = 1.0f / 121.0f;

        int pr = bid / 9;
        int b = pr / (H2 / 2);
        int yp = pr - b * (H2 / 2);
        int y0 = 2 * yp;
        int x = tid;
        const float* lgB = g_lg + b * H2 * W2;
        const float* rgB = g_rg + b * H2 * W2;

        float lgR[12];
        float cr0 = 0.f, cr20 = 0.f, cl0 = 0.f, cl20 = 0.f;
        float rv0 = 0.f, rv11 = 0.f;
#pragma unroll
        for (int r = 0; r < 12; r++) {
            int yy = y0 + r - 5;
            float lv = 0.f, rv = 0.f;
            if (yy >= 0 && yy < H2) { lv = lgB[yy * W2 + x]; rv = rgB[yy * W2 + x]; }
            lgR[r] = lv;
            rgS[r * 528 + x + 24] = rv;
            if (x < 24) { rgS[r * 528 + x] = 0.f; rgS[r * 528 + x + 504] = 0.f; }
            if (r < 11) { cr0 += rv; cr20 += rv * rv; cl0 += lv; cl20 += lv * lv; }
            if (r == 0) rv0 = rv;
            if (r == 11) rv11 = rv;
        }
        float cr1 = cr0 - rv0 + rv11;
        float cr21 = cr20 - rv0 * rv0 + rv11 * rv11;
        float cl1 = cl0 - lgR[0] + lgR[11];
        float cl21 = cl20 - lgR[0] * lgR[0] + lgR[11] * lgR[11];

        crp0[x + 40] = cr0; cr2p0[x + 40] = cr20;
        crp1[x + 40] = cr1; cr2p1[x + 40] = cr21;
        clp0[x + 40] = cl0; cl2p0[x + 40] = cl20;
        clp1[x + 40] = cl1; cl2p1[x + 40] = cl21;
        if (x < 40) {
            crp0[x] = 0.f; cr2p0[x] = 0.f; crp1[x] = 0.f; cr2p1[x] = 0.f;
            clp0[x] = 0.f; cl2p0[x] = 0.f; clp1[x] = 0.f; cl2p1[x] = 0.f;
        }
        if (x >= 440) {
            crp0[x + 80] = 0.f; cr2p0[x + 80] = 0.f; crp1[x + 80] = 0.f; cr2p1[x + 80] = 0.f;
            clp0[x + 80] = 0.f; cl2p0[x + 80] = 0.f; clp1[x + 80] = 0.f; cl2p1[x + 80] = 0.f;
        }
        __syncthreads();

        // Hcr[i] = 11-box of cr centered at col i-24 : taps crp[i+11..i+21]
        for (int i = x; i < 528; i += 480) {
            float s0 = 0.f, s20 = 0.f, s1 = 0.f, s21 = 0.f;
#pragma unroll
            for (int k = 0; k < 11; k++) {
                s0 += crp0[i + 11 + k]; s20 += cr2p0[i + 11 + k];
                s1 += crp1[i + 11 + k]; s21 += cr2p1[i + 11 + k];
            }
            Hcr0[i] = s0; Hcr20[i] = s20; Hcr1[i] = s1; Hcr21[i] = s21;
        }
        // left stats for both rows
        float lm0 = 0.f, lq0 = 0.f, lm1 = 0.f, lq1 = 0.f;
#pragma unroll
        for (int k = 0; k < 11; k++) {
            lm0 += clp0[x + 35 + k]; lq0 += cl2p0[x + 35 + k];
            lm1 += clp1[x + 35 + k]; lq1 += cl2p1[x + 35 + k];
        }
        lm0 *= NORM; lq0 *= NORM; lm1 *= NORM; lq1 *= NORM;
        float ls0 = sqrtf(fmaxf(lq0 - lm0 * lm0, 1e-8f));
        float ls1 = sqrtf(fmaxf(lq1 - lm1 * lm1, 1e-8f));
        __syncthreads();   // clp reads done; ccS region now free

        // zero ccS pads (idx 0..7, 488..495)
        if (x < 8) {
#pragma unroll
            for (int rr = 0; rr < 2; rr++)
#pragma unroll
                for (int j = 0; j < 6; j++) {
                    ccS[rr * 2976 + j * 496 + x] = 0.f;
                    ccS[rr * 2976 + j * 496 + 488 + x] = 0.f;
                }
        }

        // division-free argmax state
        float bestN0 = -1.f, bestDen0 = 1.f, bestD0 = 0.f;
        float bestN1 = -1.f, bestDen1 = 1.f, bestD1 = 0.f;
        bool interior = (x >= 5 && x < 475);
        for (int g = 0; g < 8; g++) {
            float cc0r[6], cc1r[6];
#pragma unroll
            for (int j = 0; j < 6; j++) {
                int idx = g * 6 + j;
                int d = (idx < 24) ? (idx - 24) : (idx - 23);
                int u = x + d + 24;
                float w0v = rgS[u];
                float s = lgR[0] * w0v;
#pragma unroll
                for (int r = 1; r < 11; r++) s += lgR[r] * rgS[r * 528 + u];
                cc0r[j] = s;
                float w11v = rgS[11 * 528 + u];
                cc1r[j] = s - lgR[0] * w0v + lgR[11] * w11v;
                ccS[j * 496 + x + 8] = s;
                ccS[2976 + j * 496 + x + 8] = cc1r[j];
            }
            __syncthreads();
#pragma unroll
            for (int j = 0; j < 6; j++) {
                int idx = g * 6 + j;
                int d = (idx < 24) ? (idx - 24) : (idx - 23);
                const float* c0 = ccS + j * 496;
                const float* c1 = ccS + 2976 + j * 496;
                float cross0 = cc0r[j], cross1 = cc1r[j];
#pragma unroll
                for (int k = -5; k < 0; k++) { cross0 += c0[x + 8 + k]; cross1 += c1[x + 8 + k]; }
#pragma unroll
                for (int k = 1; k <= 5; k++) { cross0 += c0[x + 8 + k]; cross1 += c1[x + 8 + k]; }
                float rm0_, r20_, rm1_, r21_;
                if (interior) {
                    int u = x + d + 24;
                    rm0_ = Hcr0[u]; r20_ = Hcr20[u]; rm1_ = Hcr1[u]; r21_ = Hcr21[u];
                } else {
                    rm0_ = 0.f; r20_ = 0.f; rm1_ = 0.f; r21_ = 0.f;
#pragma unroll
                    for (int k = -5; k <= 5; k++) {
                        int uu = x + k;
                        if (uu >= 0 && uu < W2) {
                            rm0_ += crp0[uu + d + 40]; r20_ += cr2p0[uu + d + 40];
                            rm1_ += crp1[uu + d + 40]; r21_ += cr2p1[uu + d + 40];
                        }
                    }
                }
                float rm = rm0_ * NORM;
                float rstd = sqrtf(fmaxf(r20_ * NORM - rm * rm, 1e-8f));
                float num = cross0 * NORM - lm0 * rm;
                float den = ls0 * rstd + 1e-8f;
                if (num * bestDen0 > bestN0 * den) { bestN0 = num; bestDen0 = den; bestD0 = (float)d; }
                rm = rm1_ * NORM;
                rstd = sqrtf(fmaxf(r21_ * NORM - rm * rm, 1e-8f));
                num = cross1 * NORM - lm1 * rm;
                den = ls1 * rstd + 1e-8f;
                if (num * bestDen1 > bestN1 * den) { bestN1 = num; bestDen1 = den; bestD1 = (float)d; }
            }
            __syncthreads();
        }

        // ---- sign/magnitude directly from register-resident (nc, nd) ----
        float sS = 0.f, sM = 0.f, sA = 0.f;
#pragma unroll
        for (int k = 0; k < 2; k++) {
            float ncv = (k == 0) ? fmaxf(bestN0 / bestDen0, 0.f) : fmaxf(bestN1 / bestDen1, 0.f);
            float ndv = ((k == 0) ? bestD0 : bestD1) * 2.0f;
            if (ncv > 0.3f) {
                float sgn = (ndv > 0.f) ? 1.f : ((ndv < 0.f) ? -1.f : 0.f);
#pragma unroll
                for (int r = 0; r < 2; r++) {
                    int row = 2 * (y0 + k) + r;
                    float2 p = *(const float2*)(pred + (b * HH + row) * WW + 2 * x);
                    sA += 2.f;
                    sS += fmaxf(-p.x * sgn, 0.f) + fmaxf(-p.y * sgn, 0.f);
                    sM += ncv * (fabsf(p.x - ndv) + fabsf(p.y - ndv));
                }
            }
        }
        float v;
        v = blockReduceSum(sS, sbuf); if (tid == 0) atomicAdd(&g_acc[4 * 16], (double)v);
        v = blockReduceSum(sM, sbuf); if (tid == 0) atomicAdd(&g_acc[5 * 16], (double)v);
        v = blockReduceSum(sA, sbuf); if (tid == 0) atomicAdd(&g_acc[6 * 16], (double)v);
    } else {
        // ================= TILE path (photometric + GT + smoothness) =================
        float* lS = sm;            // [3][6][122]: c*732 + r*122 + col
        float* wS = sm + 2196;
        float* dS = sm + 4392;     // [6][122]

        int t = bid - bid / 9 - 1;         // 0..4351
        int tilex = t % 8;
        int tiley = (t / 8) % 136;
        int b = t / (8 * 136);
        int tx0 = tilex * 120, ty0 = tiley * 4;

        // halo fill: 6 rows x 122 cols, warp-on-the-fly
        for (int i = tid; i < 6 * 122; i += 480) {
            int col = i % 122;
            int rrow = i / 122;
            int gx = tx0 + col - 1, gy = ty0 + rrow - 1;
            if (gx >= 0 && gx < WW && gy >= 0 && gy < HH) {
                float disp = pred[(b * HH + gy) * WW + gx];
                dS[rrow * 122 + col] = disp;
                float xs = (float)gx - disp;
                float xc = fminf(fmaxf(xs, 0.f), (float)(WW - 1));
                float x0f = floorf(xc);
                float w = xc - x0f;
                int x0i = (int)x0f;
                int x1i = min(x0i + 1, WW - 1);
#pragma unroll
                for (int c = 0; c < 3; c++) {
                    const float* R = right + ((b * 3 + c) * HH + gy) * WW;
                    wS[c * 732 + rrow * 122 + col] = R[x0i] * (1.f - w) + R[x1i] * w;
                    lS[c * 732 + rrow * 122 + col] = left[((b * 3 + c) * HH + gy) * WW + gx];
                }
            } else {
                dS[rrow * 122 + col] = 0.f;
#pragma unroll
                for (int c = 0; c < 3; c++) {
                    wS[c * 732 + rrow * 122 + col] = 0.f;
                    lS[c * 732 + rrow * 122 + col] = 0.f;
                }
            }
        }
        __syncthreads();

        int ltx = tid % 120, lty = tid / 120;
        int gx = tx0 + ltx, gy = ty0 + lty;

        float ssSum = 0.f, l1Sum = 0.f, idxSum = 0.f, idySum = 0.f;
        const float N9 = 1.f / 9.f;
        const float C1 = 1e-4f, C2 = 9e-4f;
#pragma unroll
        for (int c = 0; c < 3; c++) {
            const float* lC = lS + c * 732;
            const float* wC = wS + c * 732;
            float sx = 0.f, sy = 0.f, sxx = 0.f, syy = 0.f, sxy = 0.f;
#pragma unroll
            for (int dy = 0; dy < 3; dy++)
#pragma unroll
                for (int dx = 0; dx < 3; dx++) {
                    float xv = lC[(lty + dy) * 122 + ltx + dx];
                    float yv = wC[(lty + dy) * 122 + ltx + dx];
                    sx += xv; sy += yv;
                    sxx += xv * xv; syy += yv * yv; sxy += xv * yv;
                }
            float mx = sx * N9, my = sy * N9;
            float vx = fmaxf(sxx * N9 - mx * mx, 0.f);
            float vy = fmaxf(syy * N9 - my * my, 0.f);
            float cxy = sxy * N9 - mx * my;
            float nn = (2.f * mx * my + C1) * (2.f * cxy + C2);
            float dd = (mx * mx + my * my + C1) * (vx + vy + C2);
            ssSum += fminf(fmaxf((1.f - nn / dd) * 0.5f, 0.f), 1.f);
            float lc = lC[(lty + 1) * 122 + ltx + 1];
            float wc = wC[(lty + 1) * 122 + ltx + 1];
            l1Sum += fabsf(lc - wc);
            idxSum += fabsf(lC[(lty + 1) * 122 + ltx + 2] - lc);
            idySum += fabsf(lC[(lty + 2) * 122 + ltx + 1] - lc);
        }
        float dcen = dS[(lty + 1) * 122 + ltx + 1];
        float xs = (float)gx - dcen;
        float valid = (xs > 0.f && xs < (float)(WW - 1)) ? 1.f : 0.f;
        float perr = (0.85f * (ssSum * (1.f / 3.f)) + 0.15f * (l1Sum * (1.f / 3.f))) * valid;

        int gi = (b * HH + gy) * WW + gx;
        float g = gt[gi];
        float trust = (g > 2.f) ? conf[gi] * occ[gi] : 0.f;
        float gtn = trust * fabsf(dcen - g);

        float a_sx = 0.f, a_sy = 0.f;
        if (gx < WW - 1) {
            float ddx = fabsf(dS[(lty + 1) * 122 + ltx + 2] - dcen);
            a_sx = ddx * __expf(-idxSum * (1.f / 3.f));
        }
        if (gy < HH - 1) {
            float ddy = fabsf(dS[(lty + 2) * 122 + ltx + 1] - dcen);
            a_sy = ddy * __expf(-idySum * (1.f / 3.f));
        }

        __syncthreads();
        float v;
        v = blockReduceSum(gtn, sbuf);   if (tid == 0) atomicAdd(&g_acc[0 * 16], (double)v);
        v = blockReduceSum(trust, sbuf); if (tid == 0) atomicAdd(&g_acc[1 * 16], (double)v);
        v = blockReduceSum(perr, sbuf);  if (tid == 0) atomicAdd(&g_acc[2 * 16], (double)v);
        v = blockReduceSum(valid, sbuf); if (tid == 0) atomicAdd(&g_acc[3 * 16], (double)v);
        v = blockReduceSum(a_sx, sbuf);  if (tid == 0) atomicAdd(&g_acc[7 * 16], (double)v);
        v = blockReduceSum(a_sy, sbuf);  if (tid == 0) atomicAdd(&g_acc[8 * 16], (double)v);
    }

    // ---- finalize (last of ALL blocks) ----
    if (tid == 0) {
        __threadfence();
        int c = atomicAdd(&g_counter, 1);
        lastFlag = (c == TOTAL_BLOCKS - 1) ? 1 : 0;
    }
    __syncthreads();
    if (lastFlag && tid == 0) {
        __threadfence();
        double gtl = g_acc[0 * 16] / fmax(g_acc[1 * 16], 1.0);
        double photo = g_acc[2 * 16] / fmax(g_acc[3 * 16], 1.0);
        double n = fmax(g_acc[6 * 16], 1.0);
        double signmag = 0.3 * (g_acc[4 * 16] / n) + 0.7 * (g_acc[5 * 16] / n);
        double smooth = g_acc[7 * 16] / ((double)BB * HH * (WW - 1)) +
                        g_acc[8 * 16] / ((double)BB * (HH - 1) * WW);
        out[0] = (float)(1.0 * gtl + 1.0 * photo + 0.5 * signmag + 0.1 * smooth);
        g_counter = 0;
    }
}

// ---------------- launch ----------------
extern "C" void kernel_launch(void* const* d_in, const int* in_sizes, int n_in,
                              void* d_out, int out_size) {
    const float* pred  = (const float*)d_in[0];
    const float* gt    = (const float*)d_in[1];
    const float* conf  = (const float*)d_in[2];
    const float* occ   = (const float*)d_in[3];
    const float* left  = (const float*)d_in[4];
    const float* right = (const float*)d_in[5];
    float* out = (float*)d_out;

    downsample_kernel<<<(BB * H2 * (W2 / 2) + 255) / 256, 256>>>(left, right);
    mega_kernel<<<TOTAL_BLOCKS, 480>>>(pred, gt, conf, occ, left, right, out);
}